// round 16
// baseline (speedup 1.0000x reference)
#include <cuda_runtime.h>
#include <cstdint>

// VectorQuantizer: x [32,64,64,64] fp32, emb [512,64] fp32.
// Per pixel: argmin_k fl(fl(xsq+esq[k]) - 2*dot), dot = sequential ascending-d FMA chain.
// Then out[b,:,h,w] = emb[argmin].
//
// Round 16: R15 (1.0 B/FMA, 8px x 16codes FFMA2 tile) had 4-way bank conflicts on the
// x loads (64B lane stride). Fix: swizzled x storage xd_sw[d][l][pxg] so load l is
// base + l*256B + pxg*16B -> lanes contiguous 16B stride, conflict-free (e loads are
// half-warp broadcast already). Inner loop: 8 LDS.128 + 64 FFMA2 per d, zero MOVs.
// Block 256 thr, tile 128 px x 256 codes, NKT=2, 1 block/SM, launch_bounds(256,1).

#define KCODES 512
#define DDIM   64
#define PT     128
#define KT     256
#define NKT    (KCODES / KT)   // 2
#define NTHR   256

// dynamic smem layout (bytes)
#define XD_OFF     0                          // 16B entries xd_sw[64][4][16] = 65536
#define EP_OFF     65536                      // float2 ep[64][128] = 65536  ({e2k,e2k+1})
#define XSQ_OFF    (EP_OFF + 65536)           // float xsq[128]     = 512
#define ESQ_OFF    (XSQ_OFF + 512)            // float esq_all[512] = 2048
#define WIDX_OFF   (ESQ_OFF + 2048)           // int   widx[128]    = 512
#define SMEM_BYTES (WIDX_OFF + 512)           // 134144 <= ~227KB max dyn smem
// reduction arrays overlay xd after the mainloop:
#define RVAL_OFF   XD_OFF                     // float red_val[128][16] = 8192
#define RIDX_OFF   (XD_OFF + 8192)            // int   red_idx[128][16] = 8192

#define FMA2(acc, a, b) \
    asm("fma.rn.f32x2 %0, %1, %2, %0;" : "+l"(acc) : "l"(a), "l"(b))

__global__ __launch_bounds__(NTHR, 1)
void vq_kernel(const float* __restrict__ x,
               const float* __restrict__ emb,
               float* __restrict__ out,
               int HW, int CHW)
{
    extern __shared__ char smem_raw[];
    // xd_sw: 16B entry index (d*64 + l*16 + pxg) holds pixels (pxg*8+2l, pxg*8+2l+1),
    // each duplicated {v,v}. As float2*, entry e -> elements 2e (first px), 2e+1 (second).
    float2* xd      = (float2*)(smem_raw + XD_OFF);
    float2* ep      = (float2*)(smem_raw + EP_OFF);    // ep[d*128 + kp] = {e[2kp], e[2kp+1]}
    float*  xsq     = (float*)(smem_raw + XSQ_OFF);
    float*  esq_all = (float*)(smem_raw + ESQ_OFF);
    int*    widx    = (int*)(smem_raw + WIDX_OFF);
    float*  red_val = (float*)(smem_raw + RVAL_OFF);
    int*    red_idx = (int*)(smem_raw + RIDX_OFF);

    const int t   = threadIdx.x;
    const int n0  = blockIdx.x * PT;
    const int b   = n0 >> 12;          // HW = 4096; tiles never cross batch
    const int hw0 = n0 & 4095;

    // ---- stage x tile DUPLICATED + SWIZZLED (coalesced gmem reads) ----
    // pixel p, channel c -> float2 index (c*64 + ((p>>1)&3)*16 + (p>>3))*2 + (p&1)
    const float* xb = x + (size_t)b * CHW + hw0;
    #pragma unroll
    for (int it = 0; it < (DDIM * PT) / NTHR; ++it) {   // 32 iters
        int lin = it * NTHR + t;
        int c = lin >> 7;
        int p = lin & 127;
        float v = xb[c * HW + p];
        int ent = c * 64 + ((p >> 1) & 3) * 16 + (p >> 3);
        xd[ent * 2 + (p & 1)] = make_float2(v, v);
    }

    // ---- esq for ALL 512 codes, once (ascending d, rounded mul then add) ----
    #pragma unroll
    for (int kk = 0; kk < 2; ++kk) {
        int k = t * 2 + kk;
        const float4* er = (const float4*)(emb + (size_t)k * DDIM);
        float s = 0.0f;
        #pragma unroll
        for (int q = 0; q < DDIM / 4; ++q) {
            float4 v = er[q];
            s = __fadd_rn(s, __fmul_rn(v.x, v.x));
            s = __fadd_rn(s, __fmul_rn(v.y, v.y));
            s = __fadd_rn(s, __fmul_rn(v.z, v.z));
            s = __fadd_rn(s, __fmul_rn(v.w, v.w));
        }
        esq_all[k] = s;
    }
    __syncthreads();

    // ---- ||x||^2 per pixel (ascending d, rounded mul then add) ----
    if (t < PT) {
        int l = (t >> 1) & 3, pg = t >> 3, half = t & 1;
        float s = 0.0f;
        #pragma unroll 8
        for (int d = 0; d < DDIM; ++d) {
            float v = xd[(d * 64 + l * 16 + pg) * 2 + half].x;
            s = __fadd_rn(s, __fmul_rn(v, v));
        }
        xsq[t] = s;
    }

    const int pxg = t & 15;    // 16 groups x 8 pixels
    const int kgg = t >> 4;    // 16 groups x 16 codes (8 pairs)

    float best[8];
    int   bidx[8];
    #pragma unroll
    for (int i = 0; i < 8; ++i) { best[i] = 3.4e38f; bidx[i] = 0; }

    for (int kt = 0; kt < NKT; ++kt) {
        __syncthreads();   // xsq/xd ready (1st iter) / protect ep reuse
        // ---- stage e tile as natural pairs: ep[d][kp] = {e[2kp], e[2kp+1]} ----
        #pragma unroll
        for (int it = 0; it < (KT * DDIM / 4) / NTHR; ++it) {  // 16 iters
            int lin = it * NTHR + t;          // 0..4095
            int k   = lin >> 4;               // 0..255
            int d4  = (lin & 15) * 4;
            float4 ev = *(const float4*)(emb + (size_t)(kt * KT + k) * DDIM + d4);
            int kp = k >> 1, half = k & 1;
            ((float*)&ep[(d4 + 0) * 128 + kp])[half] = ev.x;
            ((float*)&ep[(d4 + 1) * 128 + kp])[half] = ev.y;
            ((float*)&ep[(d4 + 2) * 128 + kp])[half] = ev.z;
            ((float*)&ep[(d4 + 3) * 128 + kp])[half] = ev.w;
        }
        __syncthreads();

        // ---- mainloop: 8 LDS.128 (all conflict-free/broadcast) + 64 FFMA2 per d ----
        uint64_t acc[8][8];   // acc[i][j] = {sum x_i*e_{2j}, sum x_i*e_{2j+1}}
        #pragma unroll
        for (int i = 0; i < 8; ++i)
            #pragma unroll
            for (int j = 0; j < 8; ++j) acc[i][j] = 0ull;

        const ulonglong2* xvp = (const ulonglong2*)xd + pxg;          // +l*16 per load
        const ulonglong2* evp = (const ulonglong2*)((const uint64_t*)ep + kgg * 8);

        #pragma unroll 1
        for (int d = 0; d < DDIM; ++d) {
            const ulonglong2* xp  = xvp + d * 64;
            const ulonglong2* epr = evp + d * 64;
            ulonglong2 xa = xp[0],  xb2_ = xp[16], xc = xp[32], xd2 = xp[48];
            ulonglong2 ea = epr[0], eb = epr[1],   ec = epr[2], ed = epr[3];
            uint64_t x0 = xa.x,  x1 = xa.y,  x2 = xb2_.x, x3 = xb2_.y;
            uint64_t x4 = xc.x,  x5 = xc.y,  x6 = xd2.x,  x7 = xd2.y;
            uint64_t e0 = ea.x,  e1 = ea.y,  e2 = eb.x,   e3 = eb.y;
            uint64_t e4 = ec.x,  e5 = ec.y,  e6 = ed.x,   e7 = ed.y;
            FMA2(acc[0][0], x0, e0); FMA2(acc[0][1], x0, e1);
            FMA2(acc[0][2], x0, e2); FMA2(acc[0][3], x0, e3);
            FMA2(acc[0][4], x0, e4); FMA2(acc[0][5], x0, e5);
            FMA2(acc[0][6], x0, e6); FMA2(acc[0][7], x0, e7);
            FMA2(acc[1][0], x1, e0); FMA2(acc[1][1], x1, e1);
            FMA2(acc[1][2], x1, e2); FMA2(acc[1][3], x1, e3);
            FMA2(acc[1][4], x1, e4); FMA2(acc[1][5], x1, e5);
            FMA2(acc[1][6], x1, e6); FMA2(acc[1][7], x1, e7);
            FMA2(acc[2][0], x2, e0); FMA2(acc[2][1], x2, e1);
            FMA2(acc[2][2], x2, e2); FMA2(acc[2][3], x2, e3);
            FMA2(acc[2][4], x2, e4); FMA2(acc[2][5], x2, e5);
            FMA2(acc[2][6], x2, e6); FMA2(acc[2][7], x2, e7);
            FMA2(acc[3][0], x3, e0); FMA2(acc[3][1], x3, e1);
            FMA2(acc[3][2], x3, e2); FMA2(acc[3][3], x3, e3);
            FMA2(acc[3][4], x3, e4); FMA2(acc[3][5], x3, e5);
            FMA2(acc[3][6], x3, e6); FMA2(acc[3][7], x3, e7);
            FMA2(acc[4][0], x4, e0); FMA2(acc[4][1], x4, e1);
            FMA2(acc[4][2], x4, e2); FMA2(acc[4][3], x4, e3);
            FMA2(acc[4][4], x4, e4); FMA2(acc[4][5], x4, e5);
            FMA2(acc[4][6], x4, e6); FMA2(acc[4][7], x4, e7);
            FMA2(acc[5][0], x5, e0); FMA2(acc[5][1], x5, e1);
            FMA2(acc[5][2], x5, e2); FMA2(acc[5][3], x5, e3);
            FMA2(acc[5][4], x5, e4); FMA2(acc[5][5], x5, e5);
            FMA2(acc[5][6], x5, e6); FMA2(acc[5][7], x5, e7);
            FMA2(acc[6][0], x6, e0); FMA2(acc[6][1], x6, e1);
            FMA2(acc[6][2], x6, e2); FMA2(acc[6][3], x6, e3);
            FMA2(acc[6][4], x6, e4); FMA2(acc[6][5], x6, e5);
            FMA2(acc[6][6], x6, e6); FMA2(acc[6][7], x6, e7);
            FMA2(acc[7][0], x7, e0); FMA2(acc[7][1], x7, e1);
            FMA2(acc[7][2], x7, e2); FMA2(acc[7][3], x7, e3);
            FMA2(acc[7][4], x7, e4); FMA2(acc[7][5], x7, e5);
            FMA2(acc[7][6], x7, e6); FMA2(acc[7][7], x7, e7);
        }

        // ---- fold: s = fmaf(-2, dot, fl(xsq+esq)); ascending k keeps lowest idx ----
        #pragma unroll
        for (int j = 0; j < 8; ++j) {
            int   k0  = kt * KT + kgg * 16 + 2 * j;
            float eq0 = esq_all[k0];
            float eq1 = esq_all[k0 + 1];
            #pragma unroll
            for (int i = 0; i < 8; ++i) {
                float lo, hi;
                asm("mov.b64 {%0, %1}, %2;" : "=f"(lo), "=f"(hi) : "l"(acc[i][j]));
                float xq = xsq[pxg * 8 + i];
                float s0 = __fmaf_rn(-2.0f, lo, __fadd_rn(xq, eq0));
                float s1 = __fmaf_rn(-2.0f, hi, __fadd_rn(xq, eq1));
                if (s0 < best[i]) { best[i] = s0; bidx[i] = k0; }
                if (s1 < best[i]) { best[i] = s1; bidx[i] = k0 + 1; }
            }
        }
    }

    // ---- cross-thread argmin reduction (red arrays overlay xd; xd dead now) ----
    __syncthreads();
    #pragma unroll
    for (int i = 0; i < 8; ++i) {
        red_val[(pxg * 8 + i) * 16 + kgg] = best[i];
        red_idx[(pxg * 8 + i) * 16 + kgg] = bidx[i];
    }
    __syncthreads();
    if (t < PT) {
        float bv = red_val[t * 16 + 0];
        int   bi = red_idx[t * 16 + 0];
        #pragma unroll
        for (int g = 1; g < 16; ++g) {
            float v  = red_val[t * 16 + g];
            int   id = red_idx[t * 16 + g];
            if (v < bv || (v == bv && id < bi)) { bv = v; bi = id; }
        }
        widx[t] = bi;
    }
    __syncthreads();

    // ---- gather + write out[b, c, hw0+p] = emb[widx[p]][c] ----
    float* ob = out + (size_t)b * CHW + hw0;
    #pragma unroll
    for (int it = 0; it < (DDIM * PT) / NTHR; ++it) {
        int lin = it * NTHR + t;
        int c = lin >> 7;
        int p = lin & 127;
        ob[c * HW + p] = emb[(size_t)widx[p] * DDIM + c];
    }
}

extern "C" void kernel_launch(void* const* d_in, const int* in_sizes, int n_in,
                              void* d_out, int out_size)
{
    const float* x   = (const float*)d_in[0];   // [32, 64, 64, 64]
    const float* emb = (const float*)d_in[1];   // [512, 64]
    float* out = (float*)d_out;

    const int HW  = 64 * 64;             // 4096
    const int CHW = DDIM * HW;           // 262144
    const int N   = in_sizes[0] / DDIM;  // 131072 pixels

    cudaFuncSetAttribute(vq_kernel, cudaFuncAttributeMaxDynamicSharedMemorySize,
                         SMEM_BYTES);

    dim3 grid(N / PT);                   // 1024
    dim3 block(NTHR);
    vq_kernel<<<grid, block, SMEM_BYTES>>>(x, emb, out, HW, CHW);
}